// round 6
// baseline (speedup 1.0000x reference)
#include <cuda_runtime.h>
#include <math.h>

#define BATCH 128
#define HH 512
#define WW 512
#define HW (HH*WW)
#define W4R (WW/4)               // 128 float4 per image row

#define TILE 64                  // 64x64 tiles
#define KFUSE 5
#define ROWS 74                  // tile + 2*5 halo rows
#define STR 80                   // padded col stride in floats (left halo 8)
#define VPRX (STR/4)             // 20 float4 per row
#define THREADS 384
#define NCOL 18                  // active f4 columns v = 1..18
#define NG 18                    // row groups
#define RPG 4                    // rows per group (18*4 = 72 sweep rows)
#define SMEM_BYTES (2*ROWS*STR*4)   // 47,360 B dynamic

#define CPB 64                   // stencil CTAs per batch (8x8)

// ---- scratch (device globals: allocation-free per harness rules) ----
__device__ float g_RA[(size_t)BATCH*HW];
__device__ float g_RB[(size_t)BATCH*HW];
__device__ float g_walk[(size_t)BATCH*HW];
__device__ float g_keys[BATCH];
__device__ float g_door[BATCH];
__device__ float g_partial[BATCH*CPB];

// ---------------------------------------------------------------
__global__ void zero_kernel(float4* __restrict__ p, long long n4) {
    long long i = (long long)blockIdx.x*blockDim.x + threadIdx.x;
    long long stride = (long long)gridDim.x*blockDim.x;
    float4 z = make_float4(0.f,0.f,0.f,0.f);
    for (; i < n4; i += stride) p[i] = z;
}

__global__ void seed_kernel(const int* __restrict__ start, float* __restrict__ R) {
    int b = threadIdx.x;
    if (b < BATCH) {
        int r = start[2*b], c = start[2*b+1];
        R[(size_t)b*HW + (size_t)r*WW + c] = 1.0f;
        g_keys[b] = 0.0f;
        for (int j = 0; j < CPB; ++j) g_partial[b*CPB + j] = 0.0f;
    }
}

// keys += sum(partials); zero partials; door_pass = sigmoid(kg*(keys-1))
__global__ void door_kernel(const float* __restrict__ kg) {
    int b = threadIdx.x;
    if (b < BATCH) {
        float s = 0.0f;
        for (int j = 0; j < CPB; ++j) {
            s += g_partial[b*CPB + j];
            g_partial[b*CPB + j] = 0.0f;
        }
        g_keys[b] += s;
        float x = kg[0] * (g_keys[b] - 1.0f);
        g_door[b] = 1.0f / (1.0f + expf(-x));
    }
}

// walk = 0.25 * floor * (1 - locked + locked*door_pass)   (0.25 folded in)
__global__ void walk_kernel(const float4* __restrict__ fl,
                            const float4* __restrict__ lk,
                            float4* __restrict__ wk) {
    int b = blockIdx.y;
    float dp = g_door[b];
    size_t base = (size_t)b * (HW/4);
    int i = blockIdx.x*blockDim.x + threadIdx.x;
    int stride = gridDim.x*blockDim.x;
    for (; i < HW/4; i += stride) {
        float4 f = fl[base + i];
        float4 l = lk[base + i];
        float4 w;
        w.x = 0.25f * f.x * (1.0f - l.x + l.x*dp);
        w.y = 0.25f * f.y * (1.0f - l.y + l.y*dp);
        w.z = 0.25f * f.z * (1.0f - l.z + l.z*dp);
        w.w = 0.25f * f.w * (1.0f - l.w + l.w*dp);
        wk[base + i] = w;
    }
}

// fused 5-iteration Jacobi stencil. 64x64 tile, halo 5, walk via LDG (L2-hot),
// 4 CTAs/SM x 384 threads. Optionally fuses key reduction on the final iter.
__global__ __launch_bounds__(THREADS, 4)
void stencil_kernel(const float* __restrict__ Rin,
                    const float4* __restrict__ walk4,
                    float* __restrict__ Rout,
                    const float4* __restrict__ keyloc4,
                    int doReduce) {
    extern __shared__ float sm[];
    float* Rs0 = sm;                 // ROWS*STR floats
    float* Rs1 = sm + ROWS*STR;
    __shared__ float sred[THREADS];

    const int b   = blockIdx.z;
    const int ty0 = blockIdx.y * TILE;
    const int tx0 = blockIdx.x * TILE;
    const int tid = threadIdx.x;

    const float4* __restrict__ Rb4 = (const float4*)(Rin + (size_t)b*HW);
    const float4* __restrict__ Wb4 = walk4   + (size_t)b*(HW/4);
    const float4* __restrict__ Kb4 = keyloc4 + (size_t)b*(HW/4);
    const int cxf4 = (tx0 - 8) / 4;  // f4 column base offset (can be negative)

    // ---- load R tile (aligned float4, in/out of image per-f4), zero Rs1 ----
    float4* Rs04 = (float4*)Rs0;
    float4* Rs14 = (float4*)Rs1;
    const float4 z4 = make_float4(0.f,0.f,0.f,0.f);
    for (int idx = tid; idx < ROWS*VPRX; idx += THREADS) {
        int y = idx / VPRX, v = idx - y*VPRX;
        int gy = ty0 + y - KFUSE;
        int gx = tx0 + 4*v - 8;
        float4 r = z4;
        if ((unsigned)gy < HH && (unsigned)gx < WW)
            r = __ldg(Rb4 + (size_t)gy*W4R + (cxf4 + v));
        Rs04[idx] = r;
        Rs14[idx] = z4;              // frame of nxt must start zero
    }
    __syncthreads();

    // ---- thread -> (column v = 1..18, row group g = 0..17, rows y0..y0+3) ----
    int v = 1 + (tid % NCOL);
    int g = tid / NCOL;
    const bool act = (g < NG);       // 324 active compute threads
    if (!act) { v = 1; g = 0; }
    const int y0 = 1 + g*RPG;        // rows in [1,72]
    const size_t colOff = (size_t)(cxf4 + v);
    const bool colIn = ((unsigned)(tx0 + 4*v - 8) < WW);   // gx bounds for this column

    float4* Ro4 = (float4*)(Rout + (size_t)b*HW);
    float acc = 0.0f;

    float* cur = Rs0;
    float* nxt = Rs1;
    #pragma unroll
    for (int it = 0; it < KFUSE; ++it) {
        const float4* __restrict__ c4 = (const float4*)cur;
        float4* __restrict__ n4p = (float4*)nxt;
        const bool last = (it == KFUSE-1);

        float4 U = c4[(y0-1)*VPRX + v];
        float4 C = c4[ y0   *VPRX + v];
        #pragma unroll
        for (int i = 0; i < RPG; ++i) {
            const int y  = y0 + i;
            const int gy = ty0 + y - KFUSE;
            float4 D = c4[(y+1)*VPRX + v];
            float  L = cur[y*STR + 4*v - 1];
            float  R = cur[y*STR + 4*v + 4];
            float4 W = z4;
            if ((unsigned)gy < HH && colIn)           // zero outside image
                W = __ldg(Wb4 + (size_t)gy*W4R + colOff);
            float4 o;
            o.x = fminf(fmaf((U.x+D.x)+(L  +C.y), W.x, C.x), 1.0f);
            o.y = fminf(fmaf((U.y+D.y)+(C.x+C.z), W.y, C.y), 1.0f);
            o.z = fminf(fmaf((U.z+D.z)+(C.y+C.w), W.z, C.z), 1.0f);
            o.w = fminf(fmaf((U.w+D.w)+(C.z+R  ), W.w, C.w), 1.0f);
            if (!last) {
                if (act) n4p[y*VPRX + v] = o;
            } else {
                // interior: v in [2,17], y in [5,68] -> stream to gmem
                if (act && v >= 2 && v <= 17 && y >= KFUSE && y <= ROWS-1-KFUSE) {
                    Ro4[(size_t)gy*W4R + colOff] = o;
                    if (doReduce) {
                        float4 k = __ldg(Kb4 + (size_t)gy*W4R + colOff);
                        acc += (o.x*k.x + o.y*k.y) + (o.z*k.z + o.w*k.w);
                    }
                }
            }
            U = C; C = D;
        }
        __syncthreads();
        float* t = cur; cur = nxt; nxt = t;
    }

    if (doReduce) {
        sred[tid] = acc;
        __syncthreads();
        // 384 -> 128 (3-way fold), then power-of-two tree
        if (tid < 128) sred[tid] = (sred[tid] + sred[tid + 128]) + sred[tid + 256];
        __syncthreads();
        for (int s = 64; s > 0; s >>= 1) {
            if (tid < s) sred[tid] += sred[tid + s];
            __syncthreads();
        }
        if (tid == 0)
            g_partial[b*CPB + blockIdx.y*8 + blockIdx.x] = sred[0];
    }
}

// out[b] = R[b, clip(goal_r), clip(goal_c)]
__global__ void gather_kernel(const float* __restrict__ R,
                              const int* __restrict__ goal,
                              float* __restrict__ out) {
    int b = threadIdx.x;
    if (b < BATCH) {
        int gr = min(max(goal[2*b],   0), HH-1);
        int gc = min(max(goal[2*b+1], 0), WW-1);
        out[b] = R[(size_t)b*HW + (size_t)gr*WW + gc];
    }
}

// ---------------------------------------------------------------
extern "C" void kernel_launch(void* const* d_in, const int* in_sizes, int n_in,
                              void* d_out, int out_size) {
    const float* floor_  = (const float*)d_in[0];
    const float* keyloc  = (const float*)d_in[1];
    const float* locked  = (const float*)d_in[2];
    const int*   start   = (const int*)  d_in[3];
    const int*   goal    = (const int*)  d_in[4];
    const float* keygate = (const float*)d_in[5];
    float* out = (float*)d_out;

    float *RA, *RB, *Wp;
    cudaGetSymbolAddress((void**)&RA, g_RA);
    cudaGetSymbolAddress((void**)&RB, g_RB);
    cudaGetSymbolAddress((void**)&Wp, g_walk);

    cudaFuncSetAttribute(stencil_kernel,
                         cudaFuncAttributeMaxDynamicSharedMemorySize, SMEM_BYTES);

    zero_kernel<<<4096, 256>>>((float4*)RA, (long long)BATCH*HW/4);
    seed_kernel<<<1, 128>>>(start, RA);

    float* cur = RA;
    float* oth = RB;
    for (int stage = 0; stage < 3; ++stage) {
        door_kernel<<<1, 128>>>(keygate);   // folds in previous stage's partials
        walk_kernel<<<dim3(32, BATCH), 256>>>((const float4*)floor_,
                                              (const float4*)locked,
                                              (float4*)Wp);
        for (int ss = 0; ss < 3; ++ss) {    // 3 super-steps x 5 fused iters = 15
            int doRed = (stage < 2 && ss == 2) ? 1 : 0;  // last stage's keys are dead
            stencil_kernel<<<dim3(WW/TILE, HH/TILE, BATCH), THREADS, SMEM_BYTES>>>(
                cur, (const float4*)Wp, oth, (const float4*)keyloc, doRed);
            float* t = cur; cur = oth; oth = t;
        }
    }
    gather_kernel<<<1, 128>>>(cur, goal, out);
}

// round 7
// speedup vs baseline: 13.7354x; 13.7354x over previous
#include <cuda_runtime.h>
#include <math.h>

#define BATCH 128
#define HH 512
#define WW 512
#define HW (HH*WW)
#define W4R (WW/4)               // 128 float4 per image row

#define TILE 64                  // 64x64 tiles, 2x2 tiles per batch window
#define KFUSE 5
#define ROWS 74                  // tile + 2*5 halo rows
#define STR 80                   // padded col stride in floats (left halo 8)
#define VPRX (STR/4)             // 20 float4 per row
#define THREADS 256
#define NCOL 18                  // active f4 columns v = 1..18
#define NG 12                    // row groups
#define RPG 6                    // rows per group (12*6 = 72 sweep rows)
#define SMEM_BYTES (2*ROWS*STR*4)   // 47,360 B dynamic

#define CPB 4                    // stencil CTAs per batch (2x2)
#define WIN 128                  // computed window per batch
#define WMARG 8                  // margin zeroed / walk-computed around window
#define WREG (WIN + 2*WMARG)     // 144
#define WF4 (WREG/4)             // 36 f4 per region row

// ---- scratch (device globals: allocation-free per harness rules) ----
__device__ float g_RA[(size_t)BATCH*HW];
__device__ float g_RB[(size_t)BATCH*HW];
__device__ float g_walk[(size_t)BATCH*HW];
__device__ float g_keys[BATCH];
__device__ float g_door[BATCH];
__device__ float g_partial[BATCH*CPB];

// window origin helpers (device): window rows [oy, oy+127], cols [ox, ox+127]
__device__ __forceinline__ int win_oy(int sr) { return sr - 64; }
__device__ __forceinline__ int win_ox(int sc) { return (sc - 64) & ~3; }

// ---------------------------------------------------------------
// zero both R buffers over window+margin region of each batch (144x144)
__global__ void zero_win_kernel(const int* __restrict__ start,
                                float4* __restrict__ RA4,
                                float4* __restrict__ RB4) {
    int b = blockIdx.y;
    int woy = win_oy(start[2*b])   - WMARG;
    int wox = win_ox(start[2*b+1]) - WMARG;
    size_t base = (size_t)b * (HW/4);
    const float4 z4 = make_float4(0.f,0.f,0.f,0.f);
    int idx = blockIdx.x*blockDim.x + threadIdx.x;
    int stride = gridDim.x*blockDim.x;
    for (; idx < WREG*WF4; idx += stride) {
        int r = idx / WF4, c = idx - r*WF4;
        int gy = woy + r, gx = wox + 4*c;
        if ((unsigned)gy < HH && (unsigned)gx < WW) {
            size_t off = base + (size_t)gy*W4R + ((wox>>2) + c);
            RA4[off] = z4;
            RB4[off] = z4;
        }
    }
}

__global__ void seed_kernel(const int* __restrict__ start, float* __restrict__ R) {
    int b = threadIdx.x;
    if (b < BATCH) {
        int r = start[2*b], c = start[2*b+1];
        R[(size_t)b*HW + (size_t)r*WW + c] = 1.0f;
        g_keys[b] = 0.0f;
        for (int j = 0; j < CPB; ++j) g_partial[b*CPB + j] = 0.0f;
    }
}

// keys += sum(partials); zero partials; door_pass = sigmoid(kg*(keys-1))
__global__ void door_kernel(const float* __restrict__ kg) {
    int b = threadIdx.x;
    if (b < BATCH) {
        float s = 0.0f;
        for (int j = 0; j < CPB; ++j) {
            s += g_partial[b*CPB + j];
            g_partial[b*CPB + j] = 0.0f;
        }
        g_keys[b] += s;
        float x = kg[0] * (g_keys[b] - 1.0f);
        g_door[b] = 1.0f / (1.0f + expf(-x));
    }
}

// walk = 0.25*floor*(1 - locked + locked*door_pass), window+margin region only
__global__ void walk_kernel(const float4* __restrict__ fl,
                            const float4* __restrict__ lk,
                            float4* __restrict__ wk,
                            const int* __restrict__ start) {
    int b = blockIdx.y;
    float dp = g_door[b];
    int woy = win_oy(start[2*b])   - WMARG;
    int wox = win_ox(start[2*b+1]) - WMARG;
    size_t base = (size_t)b * (HW/4);
    int idx = blockIdx.x*blockDim.x + threadIdx.x;
    int stride = gridDim.x*blockDim.x;
    for (; idx < WREG*WF4; idx += stride) {
        int r = idx / WF4, c = idx - r*WF4;
        int gy = woy + r, gx = wox + 4*c;
        if ((unsigned)gy < HH && (unsigned)gx < WW) {
            size_t off = base + (size_t)gy*W4R + ((wox>>2) + c);
            float4 f = fl[off];
            float4 l = lk[off];
            float4 w;
            w.x = 0.25f * f.x * (1.0f - l.x + l.x*dp);
            w.y = 0.25f * f.y * (1.0f - l.y + l.y*dp);
            w.z = 0.25f * f.z * (1.0f - l.z + l.z*dp);
            w.w = 0.25f * f.w * (1.0f - l.w + l.w*dp);
            wk[off] = w;
        }
    }
}

// fused 5-iteration Jacobi stencil over one 64x64 tile of the batch window.
// Walk preloaded to registers (R4 core). Optional fused key reduction.
__global__ __launch_bounds__(THREADS, 4)
void stencil_kernel(const float* __restrict__ Rin,
                    const float4* __restrict__ walk4,
                    float* __restrict__ Rout,
                    const float4* __restrict__ keyloc4,
                    const int* __restrict__ startc,
                    int doReduce) {
    extern __shared__ float sm[];
    float* Rs0 = sm;                 // ROWS*STR floats
    float* Rs1 = sm + ROWS*STR;
    __shared__ float sred[THREADS];

    const int b   = blockIdx.z;
    const int oy  = win_oy(startc[2*b]);
    const int ox  = win_ox(startc[2*b+1]);
    const int ty0 = oy + blockIdx.y * TILE;
    const int tx0 = ox + blockIdx.x * TILE;
    const int tid = threadIdx.x;

    const float4* __restrict__ Rb4 = (const float4*)(Rin + (size_t)b*HW);
    const float4* __restrict__ Wb4 = walk4   + (size_t)b*(HW/4);
    const float4* __restrict__ Kb4 = keyloc4 + (size_t)b*(HW/4);
    const int cxf4 = (tx0 - 8) >> 2;   // tx0-8 is a multiple of 4 (ox aligned)

    // ---- load R tile (aligned float4, zero-fill out-of-image), zero Rs1 ----
    float4* Rs04 = (float4*)Rs0;
    float4* Rs14 = (float4*)Rs1;
    const float4 z4 = make_float4(0.f,0.f,0.f,0.f);
    for (int idx = tid; idx < ROWS*VPRX; idx += THREADS) {
        int y = idx / VPRX, v = idx - y*VPRX;
        int gy = ty0 + y - KFUSE;
        int gx = tx0 + 4*v - 8;
        float4 r = z4;
        if ((unsigned)gy < HH && (unsigned)gx < WW)
            r = __ldg(Rb4 + (size_t)gy*W4R + (cxf4 + v));
        Rs04[idx] = r;
        Rs14[idx] = z4;              // frame of nxt must start zero
    }

    // ---- thread -> (column v = 1..18, row group g = 0..11, rows y0..y0+5) ----
    int v = 1 + (tid % NCOL);
    int g = tid / NCOL;
    const bool act = (g < NG);       // 216 active compute threads
    if (!act) { v = 1; g = 0; }
    const int y0 = 1 + g*RPG;        // rows in [1,72]
    const size_t colOff = (size_t)(cxf4 + v);
    const bool colIn = ((unsigned)(tx0 + 4*v - 8) < WW);

    // walk into registers (window+margin is computed; out-of-image -> 0)
    float4 Wr[RPG];
    #pragma unroll
    for (int i = 0; i < RPG; ++i) {
        int gy = ty0 + (y0 + i) - KFUSE;
        Wr[i] = z4;
        if ((unsigned)gy < HH && colIn)
            Wr[i] = __ldg(Wb4 + (size_t)gy*W4R + colOff);
    }
    __syncthreads();

    float4* Ro4 = (float4*)(Rout + (size_t)b*HW);
    float acc = 0.0f;

    float* cur = Rs0;
    float* nxt = Rs1;
    #pragma unroll
    for (int it = 0; it < KFUSE; ++it) {
        const float4* __restrict__ c4 = (const float4*)cur;
        float4* __restrict__ n4p = (float4*)nxt;
        const bool last = (it == KFUSE-1);

        float4 U = c4[(y0-1)*VPRX + v];
        float4 C = c4[ y0   *VPRX + v];
        #pragma unroll
        for (int i = 0; i < RPG; ++i) {
            const int y  = y0 + i;
            const int gy = ty0 + y - KFUSE;
            float4 D = c4[(y+1)*VPRX + v];
            float  L = cur[y*STR + 4*v - 1];
            float  R = cur[y*STR + 4*v + 4];
            float4 W = Wr[i];
            float4 o;
            o.x = fminf(fmaf((U.x+D.x)+(L  +C.y), W.x, C.x), 1.0f);
            o.y = fminf(fmaf((U.y+D.y)+(C.x+C.z), W.y, C.y), 1.0f);
            o.z = fminf(fmaf((U.z+D.z)+(C.y+C.w), W.z, C.z), 1.0f);
            o.w = fminf(fmaf((U.w+D.w)+(C.z+R  ), W.w, C.w), 1.0f);
            if (!last) {
                if (act) n4p[y*VPRX + v] = o;
            } else {
                // interior: v in [2,17], y in [5,68]; guard image bounds
                if (act && v >= 2 && v <= 17 && y >= KFUSE && y <= ROWS-1-KFUSE
                    && (unsigned)gy < HH && colIn) {
                    Ro4[(size_t)gy*W4R + colOff] = o;
                    if (doReduce) {
                        float4 k = __ldg(Kb4 + (size_t)gy*W4R + colOff);
                        acc += (o.x*k.x + o.y*k.y) + (o.z*k.z + o.w*k.w);
                    }
                }
            }
            U = C; C = D;
        }
        __syncthreads();
        float* t = cur; cur = nxt; nxt = t;
    }

    if (doReduce) {
        sred[tid] = acc;
        __syncthreads();
        for (int s = THREADS/2; s > 0; s >>= 1) {
            if (tid < s) sred[tid] += sred[tid + s];
            __syncthreads();
        }
        if (tid == 0)
            g_partial[b*CPB + blockIdx.y*2 + blockIdx.x] = sred[0];
    }
}

// out[b] = R[b, clip(goal_r), clip(goal_c)]  (zero outside window is correct)
__global__ void gather_kernel(const float* __restrict__ R,
                              const int* __restrict__ goal,
                              float* __restrict__ out) {
    int b = threadIdx.x;
    if (b < BATCH) {
        int gr = min(max(goal[2*b],   0), HH-1);
        int gc = min(max(goal[2*b+1], 0), WW-1);
        out[b] = R[(size_t)b*HW + (size_t)gr*WW + gc];
    }
}

// ---------------------------------------------------------------
extern "C" void kernel_launch(void* const* d_in, const int* in_sizes, int n_in,
                              void* d_out, int out_size) {
    const float* floor_  = (const float*)d_in[0];
    const float* keyloc  = (const float*)d_in[1];
    const float* locked  = (const float*)d_in[2];
    const int*   start   = (const int*)  d_in[3];
    const int*   goal    = (const int*)  d_in[4];
    const float* keygate = (const float*)d_in[5];
    float* out = (float*)d_out;

    float *RA, *RB, *Wp;
    cudaGetSymbolAddress((void**)&RA, g_RA);
    cudaGetSymbolAddress((void**)&RB, g_RB);
    cudaGetSymbolAddress((void**)&Wp, g_walk);

    cudaFuncSetAttribute(stencil_kernel,
                         cudaFuncAttributeMaxDynamicSharedMemorySize, SMEM_BYTES);

    // zero both R buffers on window regions only; then seed starts
    zero_win_kernel<<<dim3(8, BATCH), 256>>>(start, (float4*)RA, (float4*)RB);
    seed_kernel<<<1, 128>>>(start, RA);

    float* cur = RA;
    float* oth = RB;
    for (int stage = 0; stage < 3; ++stage) {
        door_kernel<<<1, 128>>>(keygate);   // folds in previous stage's partials
        walk_kernel<<<dim3(8, BATCH), 256>>>((const float4*)floor_,
                                             (const float4*)locked,
                                             (float4*)Wp, start);
        for (int ss = 0; ss < 3; ++ss) {    // 3 super-steps x 5 fused iters = 15
            int doRed = (stage < 2 && ss == 2) ? 1 : 0;
            stencil_kernel<<<dim3(2, 2, BATCH), THREADS, SMEM_BYTES>>>(
                cur, (const float4*)Wp, oth, (const float4*)keyloc, start, doRed);
            float* t = cur; cur = oth; oth = t;
        }
    }
    gather_kernel<<<1, 128>>>(cur, goal, out);
}

// round 8
// speedup vs baseline: 44.7282x; 3.2564x over previous
#include <cuda_runtime.h>
#include <math.h>

#define BATCH 128
#define HH 512
#define WW 512
#define HW (HH*WW)
#define W4R (WW/4)       // 128 float4 per image row

// Per-batch compute region: 98 rows x 112 cols (floats), all in one CTA's smem.
// Support after 45 iterations is the L1-ball(start,45): rows map to local
// [4,94] within compute rows [1,96]; cols to [11,104] within compute cols
// [4,107]. Frame (row 0/97, f4-col 0/27) is never written and stays zero.
#define RR 98            // region rows
#define RC 112           // region cols (floats)
#define RCF4 (RC/4)      // 28 f4 per row
#define NCOLV 26         // compute f4 columns v = 1..26
#define NGRP 32          // row groups
#define RPG 3            // rows per group: 32*3 = 96 compute rows (1..96)
#define THREADS (NCOLV*NGRP)   // 832 (26 warps)
#define SMEMB (2*RR*RC*4)      // 87,808 B dynamic

__global__ __launch_bounds__(THREADS, 1)
void fused_kernel(const float* __restrict__ floor_,
                  const float* __restrict__ keyloc,
                  const float* __restrict__ locked,
                  const int*   __restrict__ start,
                  const int*   __restrict__ goal,
                  const float* __restrict__ keygate,
                  float*       __restrict__ out)
{
    extern __shared__ float sm[];
    float* R0 = sm;                  // RR*RC
    float* R1 = sm + RR*RC;
    __shared__ float sred[1024];

    const int b  = blockIdx.x;
    const int sr = start[2*b], sc = start[2*b+1];
    const int oy = sr - 49;                 // region rows oy .. oy+97
    const int ox = (sc - 56) & ~3;          // f4-aligned; sc-ox in [56,59]
    const int tid = threadIdx.x;

    // ---- zero both buffers ----
    float4* R04 = (float4*)R0;
    float4* R14 = (float4*)R1;
    const float4 z4 = make_float4(0.f,0.f,0.f,0.f);
    for (int i = tid; i < RR*RCF4; i += THREADS) { R04[i] = z4; R14[i] = z4; }
    __syncthreads();
    if (tid == 0) R0[(sr-oy)*RC + (sc-ox)] = 1.0f;   // seed

    // ---- thread -> (f4 column v = 1..26, rows y0..y0+2 in [1,96]) ----
    const int v  = 1 + tid % NCOLV;
    const int g  = tid / NCOLV;
    const int y0 = 1 + g*RPG;
    const float kg = __ldg(keygate);
    const int gx = ox + 4*v;                          // multiple of 4
    const bool colIn = ((unsigned)gx < WW);           // whole f4 in image iff true

    const float4* F4 = (const float4*)(floor_ + (size_t)b*HW);
    const float4* L4 = (const float4*)(locked + (size_t)b*HW);
    const float4* K4 = (const float4*)(keyloc + (size_t)b*HW);
    const int cf4 = gx >> 2;

    float keys = 0.0f;
    float* cur = R0;
    float* nxt = R1;
    __syncthreads();

    #pragma unroll 1
    for (int stage = 0; stage < 3; ++stage) {
        // door gate + per-cell walk into registers (out-of-image -> 0)
        const float dp = 1.0f / (1.0f + expf(-kg*(keys - 1.0f)));
        float4 Wr[RPG];
        #pragma unroll
        for (int i = 0; i < RPG; ++i) {
            int gy = oy + y0 + i;
            Wr[i] = z4;
            if ((unsigned)gy < HH && colIn) {
                size_t off = (size_t)gy*W4R + cf4;
                float4 f = __ldg(F4 + off), l = __ldg(L4 + off);
                Wr[i].x = 0.25f*f.x*(1.0f - l.x + l.x*dp);
                Wr[i].y = 0.25f*f.y*(1.0f - l.y + l.y*dp);
                Wr[i].z = 0.25f*f.z*(1.0f - l.z + l.z*dp);
                Wr[i].w = 0.25f*f.w*(1.0f - l.w + l.w*dp);
            }
        }

        // 15 Jacobi iterations entirely in smem
        #pragma unroll 1
        for (int it = 0; it < 15; ++it) {
            const float4* c4 = (const float4*)cur;
            float4* n4 = (float4*)nxt;
            float4 U = c4[(y0-1)*RCF4 + v];
            float4 C = c4[ y0   *RCF4 + v];
            #pragma unroll
            for (int i = 0; i < RPG; ++i) {
                const int y = y0 + i;
                float4 D  = c4[(y+1)*RCF4 + v];
                float  Lh = cur[y*RC + 4*v - 1];
                float  Rh = cur[y*RC + 4*v + 4];
                float4 W  = Wr[i];
                float4 o;
                o.x = fminf(fmaf((U.x+D.x)+(Lh +C.y), W.x, C.x), 1.0f);
                o.y = fminf(fmaf((U.y+D.y)+(C.x+C.z), W.y, C.y), 1.0f);
                o.z = fminf(fmaf((U.z+D.z)+(C.y+C.w), W.z, C.z), 1.0f);
                o.w = fminf(fmaf((U.w+D.w)+(C.z+Rh ), W.w, C.w), 1.0f);
                n4[y*RCF4 + v] = o;
                U = C; C = D;
            }
            __syncthreads();
            float* t = cur; cur = nxt; nxt = t;
        }

        // fused key reduction (stage 2's keys are dead code in the reference)
        if (stage < 2) {
            float acc = 0.0f;
            const float4* c4 = (const float4*)cur;
            #pragma unroll
            for (int i = 0; i < RPG; ++i) {
                int y = y0 + i, gy = oy + y;
                if ((unsigned)gy < HH && colIn) {   // R==0 outside image anyway
                    float4 r = c4[y*RCF4 + v];
                    float4 k = __ldg(K4 + (size_t)gy*W4R + cf4);
                    acc += (r.x*k.x + r.y*k.y) + (r.z*k.z + r.w*k.w);
                }
            }
            sred[tid] = acc;
            if (tid < 1024 - THREADS) sred[THREADS + tid] = 0.0f;
            __syncthreads();
            for (int s = 512; s > 0; s >>= 1) {
                if (tid < s) sred[tid] += sred[tid + s];
                __syncthreads();
            }
            keys += sred[0];     // identical in every thread -> deterministic dp
            __syncthreads();
        }
    }

    // gather: out[b] = R at clipped goal (0 outside window == true value)
    if (tid == 0) {
        int gr = min(max(goal[2*b],   0), HH-1);
        int gc = min(max(goal[2*b+1], 0), WW-1);
        int ly = gr - oy, lx = gc - ox;
        float val = 0.0f;
        if ((unsigned)ly < RR && (unsigned)lx < RC) val = cur[ly*RC + lx];
        out[b] = val;
    }
}

// ---------------------------------------------------------------
extern "C" void kernel_launch(void* const* d_in, const int* in_sizes, int n_in,
                              void* d_out, int out_size) {
    const float* floor_  = (const float*)d_in[0];
    const float* keyloc  = (const float*)d_in[1];
    const float* locked  = (const float*)d_in[2];
    const int*   start   = (const int*)  d_in[3];
    const int*   goal    = (const int*)  d_in[4];
    const float* keygate = (const float*)d_in[5];
    float* out = (float*)d_out;

    cudaFuncSetAttribute(fused_kernel,
                         cudaFuncAttributeMaxDynamicSharedMemorySize, SMEMB);
    fused_kernel<<<BATCH, THREADS, SMEMB>>>(floor_, keyloc, locked,
                                            start, goal, keygate, out);
}

// round 9
// speedup vs baseline: 89.1137x; 1.9923x over previous
#include <cuda_runtime.h>
#include <math.h>

#define BATCH 128
#define HH 512
#define WW 512
#define HW (HH*WW)
#define W4R (WW/4)       // 128 float4 per image row

// Per-batch compute region: 98 rows x 112 cols (floats), one CTA per batch.
// Seed at local (49, sx) with sx in [56,59]. Support after k global
// iterations is the L1-diamond of radius k; threads gate compute on it.
#define RR 98            // region rows
#define RC 112           // region cols (floats)
#define RCF4 (RC/4)      // 28 f4 per row
#define NCOLV 26         // compute f4 columns v = 1..26
#define NGRP 32          // row groups
#define RPG 3            // rows per group: 32*3 = 96 compute rows (1..96)
#define THREADS (NCOLV*NGRP)   // 832 (26 warps)
#define SMEMB (2*RR*RC*4)      // 87,808 B dynamic

__global__ __launch_bounds__(THREADS, 1)
void fused_kernel(const float* __restrict__ floor_,
                  const float* __restrict__ keyloc,
                  const float* __restrict__ locked,
                  const int*   __restrict__ start,
                  const int*   __restrict__ goal,
                  const float* __restrict__ keygate,
                  float*       __restrict__ out)
{
    extern __shared__ float sm[];
    float* R0 = sm;                  // RR*RC
    float* R1 = sm + RR*RC;
    __shared__ float sred[1024];

    const int b  = blockIdx.x;
    const int sr = start[2*b], sc = start[2*b+1];
    const int oy = sr - 49;                 // region rows oy .. oy+97 (seed row -> local 49)
    const int ox = (sc - 56) & ~3;          // f4-aligned; sx = sc-ox in [56,59]
    const int sx = sc - ox;
    const int tid = threadIdx.x;

    // ---- zero both buffers ----
    float4* R04 = (float4*)R0;
    float4* R14 = (float4*)R1;
    const float4 z4 = make_float4(0.f,0.f,0.f,0.f);
    for (int i = tid; i < RR*RCF4; i += THREADS) { R04[i] = z4; R14[i] = z4; }
    __syncthreads();
    if (tid == 0) R0[49*RC + sx] = 1.0f;    // seed

    // ---- thread -> (f4 column v = 1..26, rows y0..y0+2 in [1,96]) ----
    const int v  = 1 + tid % NCOLV;
    const int g  = tid / NCOLV;
    const int y0 = 1 + g*RPG;
    const float kg = __ldg(keygate);
    const int gx = ox + 4*v;                // multiple of 4
    const bool colIn = ((unsigned)gx < WW); // whole f4 in image iff true

    // min L1 distance from this thread's 3x4 block to the seed (constant)
    const int dy_min = max(0, max(y0 - 49, 47 - y0));
    const int dx_min = max(0, max(4*v - sx, sx - (4*v + 3)));
    const int dmin   = dy_min + dx_min;

    const float4* F4 = (const float4*)(floor_ + (size_t)b*HW);
    const float4* L4 = (const float4*)(locked + (size_t)b*HW);
    const float4* K4 = (const float4*)(keyloc + (size_t)b*HW);
    const int cf4 = gx >> 2;

    float keys = 0.0f;
    float* cur = R0;
    float* nxt = R1;
    __syncthreads();

    #pragma unroll 1
    for (int stage = 0; stage < 3; ++stage) {
        const int kend = 15*(stage + 1);    // max radius reached this stage
        // door gate + per-cell walk into registers (gated; out-of-image -> 0)
        const float dp = 1.0f / (1.0f + expf(-kg*(keys - 1.0f)));
        float4 Wr[RPG];
        #pragma unroll
        for (int i = 0; i < RPG; ++i) Wr[i] = z4;
        if (dmin <= kend) {
            #pragma unroll
            for (int i = 0; i < RPG; ++i) {
                int gy = oy + y0 + i;
                if ((unsigned)gy < HH && colIn) {
                    size_t off = (size_t)gy*W4R + cf4;
                    float4 f = __ldg(F4 + off), l = __ldg(L4 + off);
                    Wr[i].x = 0.25f*f.x*(1.0f - l.x + l.x*dp);
                    Wr[i].y = 0.25f*f.y*(1.0f - l.y + l.y*dp);
                    Wr[i].z = 0.25f*f.z*(1.0f - l.z + l.z*dp);
                    Wr[i].w = 0.25f*f.w*(1.0f - l.w + l.w*dp);
                }
            }
        }

        // 15 Jacobi iterations entirely in smem, diamond-gated
        #pragma unroll 1
        for (int it = 0; it < 15; ++it) {
            const int k = stage*15 + it + 1;   // support radius after this iter
            if (dmin <= k) {
                const float4* c4 = (const float4*)cur;
                float4* n4 = (float4*)nxt;
                float4 U = c4[(y0-1)*RCF4 + v];
                float4 C = c4[ y0   *RCF4 + v];
                #pragma unroll
                for (int i = 0; i < RPG; ++i) {
                    const int y = y0 + i;
                    float4 D  = c4[(y+1)*RCF4 + v];
                    float  Lh = cur[y*RC + 4*v - 1];
                    float  Rh = cur[y*RC + 4*v + 4];
                    float4 W  = Wr[i];
                    float4 o;
                    o.x = fminf(fmaf((U.x+D.x)+(Lh +C.y), W.x, C.x), 1.0f);
                    o.y = fminf(fmaf((U.y+D.y)+(C.x+C.z), W.y, C.y), 1.0f);
                    o.z = fminf(fmaf((U.z+D.z)+(C.y+C.w), W.z, C.z), 1.0f);
                    o.w = fminf(fmaf((U.w+D.w)+(C.z+Rh ), W.w, C.w), 1.0f);
                    n4[y*RCF4 + v] = o;
                    U = C; C = D;
                }
            }
            __syncthreads();
            float* t = cur; cur = nxt; nxt = t;
        }

        // fused key reduction (stage 2's keys are dead code in the reference)
        if (stage < 2) {
            float acc = 0.0f;
            if (dmin <= kend) {                // R==0 beyond radius kend
                const float4* c4 = (const float4*)cur;
                #pragma unroll
                for (int i = 0; i < RPG; ++i) {
                    int y = y0 + i, gy = oy + y;
                    if ((unsigned)gy < HH && colIn) {
                        float4 r = c4[y*RCF4 + v];
                        float4 kk = __ldg(K4 + (size_t)gy*W4R + cf4);
                        acc += (r.x*kk.x + r.y*kk.y) + (r.z*kk.z + r.w*kk.w);
                    }
                }
            }
            sred[tid] = acc;
            if (tid < 1024 - THREADS) sred[THREADS + tid] = 0.0f;
            __syncthreads();
            for (int s = 512; s > 0; s >>= 1) {
                if (tid < s) sred[tid] += sred[tid + s];
                __syncthreads();
            }
            keys += sred[0];     // identical in every thread -> deterministic dp
            __syncthreads();
        }
    }

    // gather: out[b] = R at clipped goal (0 outside region == true value)
    if (tid == 0) {
        int gr = min(max(goal[2*b],   0), HH-1);
        int gc = min(max(goal[2*b+1], 0), WW-1);
        int ly = gr - oy, lx = gc - ox;
        float val = 0.0f;
        if ((unsigned)ly < RR && (unsigned)lx < RC) val = cur[ly*RC + lx];
        out[b] = val;
    }
}

// ---------------------------------------------------------------
extern "C" void kernel_launch(void* const* d_in, const int* in_sizes, int n_in,
                              void* d_out, int out_size) {
    const float* floor_  = (const float*)d_in[0];
    const float* keyloc  = (const float*)d_in[1];
    const float* locked  = (const float*)d_in[2];
    const int*   start   = (const int*)  d_in[3];
    const int*   goal    = (const int*)  d_in[4];
    const float* keygate = (const float*)d_in[5];
    float* out = (float*)d_out;

    cudaFuncSetAttribute(fused_kernel,
                         cudaFuncAttributeMaxDynamicSharedMemorySize, SMEMB);
    fused_kernel<<<BATCH, THREADS, SMEMB>>>(floor_, keyloc, locked,
                                            start, goal, keygate, out);
}

// round 10
// speedup vs baseline: 96.9111x; 1.0875x over previous
#include <cuda_runtime.h>
#include <math.h>

#define BATCH 128
#define HH 512
#define WW 512
#define HW (HH*WW)
#define W4R (WW/4)       // 128 float4 per image row

// Per-batch compute region: 98 rows x 112 cols (floats), one CTA per batch.
// Seed at local (49, sx), sx in [56,59]. Support after k global iterations
// is the L1-diamond of radius k; threads gate compute on it.
#define RR 98            // region rows
#define RC 112           // region cols (floats)
#define RCF4 (RC/4)      // 28 f4 per row
#define NCOLV 26         // compute f4 columns v = 1..26
#define NGRP 32          // row groups
#define RPG 3            // rows per group: 32*3 = 96 compute rows (1..96)
#define THREADS (NCOLV*NGRP)   // 832 (26 warps)
#define NWARP (THREADS/32)     // 26
#define SMEMB (2*RR*RC*4)      // 87,808 B dynamic

__global__ __launch_bounds__(THREADS, 1)
void fused_kernel(const float* __restrict__ floor_,
                  const float* __restrict__ keyloc,
                  const float* __restrict__ locked,
                  const int*   __restrict__ start,
                  const int*   __restrict__ goal,
                  const float* __restrict__ keygate,
                  float*       __restrict__ out)
{
    extern __shared__ float sm[];
    float* R0 = sm;                  // RR*RC
    float* R1 = sm + RR*RC;
    __shared__ float swarp[NWARP];

    const int b  = blockIdx.x;
    const int sr = start[2*b], sc = start[2*b+1];
    const int oy = sr - 49;                 // seed row -> local 49
    const int ox = (sc - 56) & ~3;          // f4-aligned; sx in [56,59]
    const int sx = sc - ox;
    const int tid  = threadIdx.x;
    const int lane = tid & 31;
    const int wid  = tid >> 5;

    // ---- zero both buffers ----
    float4* R04 = (float4*)R0;
    float4* R14 = (float4*)R1;
    const float4 z4 = make_float4(0.f,0.f,0.f,0.f);
    for (int i = tid; i < RR*RCF4; i += THREADS) { R04[i] = z4; R14[i] = z4; }
    __syncthreads();
    if (tid == 0) R0[49*RC + sx] = 1.0f;    // seed (smem)

    // ---- thread -> (f4 column v = 1..26, rows y0..y0+2 in [1,96]) ----
    const int v  = 1 + tid % NCOLV;
    const int g  = tid / NCOLV;
    const int y0 = 1 + g*RPG;
    const float kg = __ldg(keygate);
    const int gx = ox + 4*v;                // multiple of 4
    const bool colIn = ((unsigned)gx < WW);

    // min L1 distance from this thread's 3x4 block to the seed (constant)
    const int dy_min = max(0, max(y0 - 49, 47 - y0));
    const int dx_min = max(0, max(4*v - sx, sx - (4*v + 3)));
    const int dmin   = dy_min + dx_min;

    const float4* F4 = (const float4*)(floor_ + (size_t)b*HW);
    const float4* L4 = (const float4*)(locked + (size_t)b*HW);
    const float4* K4 = (const float4*)(keyloc + (size_t)b*HW);
    const int cf4 = gx >> 2;

    // register copy of this thread's 3 rows (state). Initially zero + seed.
    float4 O0 = z4, O1 = z4, O2 = z4;
    if (sr - oy >= y0 && sr - oy <= y0 + 2 && sx >= 4*v && sx <= 4*v + 3) {
        float* Op = (sr - oy == y0) ? &O0.x : (sr - oy == y0 + 1) ? &O1.x : &O2.x;
        Op[sx - 4*v] = 1.0f;
    }

    float keys = 0.0f;
    float* cur = R0;
    float* nxt = R1;
    __syncthreads();

    #pragma unroll 1
    for (int stage = 0; stage < 3; ++stage) {
        const int kend = 15*(stage + 1);
        // door gate + walk into registers (gated; out-of-image -> 0)
        const float dp = 1.0f / (1.0f + expf(-kg*(keys - 1.0f)));
        float4 Wr[RPG];
        #pragma unroll
        for (int i = 0; i < RPG; ++i) Wr[i] = z4;
        if (dmin <= kend && colIn) {
            #pragma unroll
            for (int i = 0; i < RPG; ++i) {
                int gy = oy + y0 + i;
                if ((unsigned)gy < HH) {
                    size_t off = (size_t)gy*W4R + cf4;
                    float4 f = __ldg(F4 + off), l = __ldg(L4 + off);
                    Wr[i].x = 0.25f*f.x*(1.0f - l.x + l.x*dp);
                    Wr[i].y = 0.25f*f.y*(1.0f - l.y + l.y*dp);
                    Wr[i].z = 0.25f*f.z*(1.0f - l.z + l.z*dp);
                    Wr[i].w = 0.25f*f.w*(1.0f - l.w + l.w*dp);
                }
            }
        }

        // 15 Jacobi iterations in smem; own rows carried in registers
        #pragma unroll 1
        for (int it = 0; it < 15; ++it) {
            const int k = stage*15 + it + 1;
            if (dmin <= k) {
                const float4* c4 = (const float4*)cur;
                float4* n4 = (float4*)nxt;
                float4 U = c4[(y0-1)*RCF4 + v];     // neighbor row above
                float4 D = c4[(y0+3)*RCF4 + v];     // neighbor row below
                float L0 = cur[(y0  )*RC + 4*v - 1], Rh0 = cur[(y0  )*RC + 4*v + 4];
                float L1 = cur[(y0+1)*RC + 4*v - 1], Rh1 = cur[(y0+1)*RC + 4*v + 4];
                float L2 = cur[(y0+2)*RC + 4*v - 1], Rh2 = cur[(y0+2)*RC + 4*v + 4];
                float4 N0, N1, N2;
                N0.x = fminf(fmaf((U.x +O1.x)+(L0  +O0.y), Wr[0].x, O0.x), 1.0f);
                N0.y = fminf(fmaf((U.y +O1.y)+(O0.x+O0.z), Wr[0].y, O0.y), 1.0f);
                N0.z = fminf(fmaf((U.z +O1.z)+(O0.y+O0.w), Wr[0].z, O0.z), 1.0f);
                N0.w = fminf(fmaf((U.w +O1.w)+(O0.z+Rh0 ), Wr[0].w, O0.w), 1.0f);
                N1.x = fminf(fmaf((O0.x+O2.x)+(L1  +O1.y), Wr[1].x, O1.x), 1.0f);
                N1.y = fminf(fmaf((O0.y+O2.y)+(O1.x+O1.z), Wr[1].y, O1.y), 1.0f);
                N1.z = fminf(fmaf((O0.z+O2.z)+(O1.y+O1.w), Wr[1].z, O1.z), 1.0f);
                N1.w = fminf(fmaf((O0.w+O2.w)+(O1.z+Rh1 ), Wr[1].w, O1.w), 1.0f);
                N2.x = fminf(fmaf((O1.x+D.x )+(L2  +O2.y), Wr[2].x, O2.x), 1.0f);
                N2.y = fminf(fmaf((O1.y+D.y )+(O2.x+O2.z), Wr[2].y, O2.y), 1.0f);
                N2.z = fminf(fmaf((O1.z+D.z )+(O2.y+O2.w), Wr[2].z, O2.z), 1.0f);
                N2.w = fminf(fmaf((O1.w+D.w )+(O2.z+Rh2 ), Wr[2].w, O2.w), 1.0f);
                n4[(y0  )*RCF4 + v] = N0;
                n4[(y0+1)*RCF4 + v] = N1;
                n4[(y0+2)*RCF4 + v] = N2;
                O0 = N0; O1 = N1; O2 = N2;
            }
            __syncthreads();
            float* t = cur; cur = nxt; nxt = t;
        }

        // fused key reduction (stage 2's keys are dead code in the reference)
        if (stage < 2) {
            float acc = 0.0f;
            if (dmin <= kend && colIn) {        // R==0 beyond radius kend
                #pragma unroll
                for (int i = 0; i < RPG; ++i) {
                    int gy = oy + y0 + i;
                    if ((unsigned)gy < HH) {
                        float4 r = (i == 0) ? O0 : (i == 1) ? O1 : O2;
                        float4 kk = __ldg(K4 + (size_t)gy*W4R + cf4);
                        acc += (r.x*kk.x + r.y*kk.y) + (r.z*kk.z + r.w*kk.w);
                    }
                }
            }
            // warp reduce (fixed order), then uniform cross-warp sum
            #pragma unroll
            for (int off = 16; off > 0; off >>= 1)
                acc += __shfl_down_sync(0xffffffffu, acc, off);
            if (lane == 0) swarp[wid] = acc;
            __syncthreads();
            float s = 0.0f;
            #pragma unroll
            for (int w = 0; w < NWARP; ++w) s += swarp[w];
            keys += s;                          // identical in every thread
            // no barrier needed: swarp next written >=15 barriers from now
        }
    }

    // gather: out[b] = R at clipped goal (0 outside region == true value)
    if (tid == 0) {
        int gr = min(max(goal[2*b],   0), HH-1);
        int gc = min(max(goal[2*b+1], 0), WW-1);
        int ly = gr - oy, lx = gc - ox;
        float val = 0.0f;
        if ((unsigned)ly < RR && (unsigned)lx < RC) val = cur[ly*RC + lx];
        out[b] = val;
    }
}

// ---------------------------------------------------------------
extern "C" void kernel_launch(void* const* d_in, const int* in_sizes, int n_in,
                              void* d_out, int out_size) {
    const float* floor_  = (const float*)d_in[0];
    const float* keyloc  = (const float*)d_in[1];
    const float* locked  = (const float*)d_in[2];
    const int*   start   = (const int*)  d_in[3];
    const int*   goal    = (const int*)  d_in[4];
    const float* keygate = (const float*)d_in[5];
    float* out = (float*)d_out;

    cudaFuncSetAttribute(fused_kernel,
                         cudaFuncAttributeMaxDynamicSharedMemorySize, SMEMB);
    fused_kernel<<<BATCH, THREADS, SMEMB>>>(floor_, keyloc, locked,
                                            start, goal, keygate, out);
}